// round 6
// baseline (speedup 1.0000x reference)
#include <cuda_runtime.h>
#include <math.h>

// Problem constants (fixed by the reference setup_inputs)
namespace {
constexpr int B_ = 64;    // batch
constexpr int S_ = 128;   // seq len
constexpr int D_ = 128;   // embed dim
constexpr int V_ = 512;   // vocab
constexpr int C_ = 256;   // controller size
constexpr int N_ = 256;   // memory slots
constexpr int M_ = 64;    // memory width
constexpr int PITCH = 65; // smem pitch for mem to avoid 32-way bank conflicts

constexpr int SMEM_FLOATS =
    N_ * PITCH   // mem          16640
    + 448        // xin = [emb(128) | rv(64) | h(256)]
    + N_         // wprev
    + N_         // wga (w_g then w)
    + 4 * M_     // keys, er, ad, rv
    + N_         // rvp (4x64 partials)
    + 8          // red (warp partials)
    + 8;         // sc scalars: beta, gate, gamma, knorm, shift0..2
constexpr size_t SMEM_BYTES = SMEM_FLOATS * sizeof(float);
}

__device__ __forceinline__ float sigm(float x) { return 1.0f / (1.0f + expf(-x)); }
__device__ __forceinline__ float softplus_(float x) { return log1pf(expf(x)); }

// Block-wide reductions over 256 threads (8 warps). Entry __syncthreads()
// protects `red` against the previous user still reading it.
__device__ __forceinline__ float blk_sum(float v, float* red) {
#pragma unroll
    for (int o = 16; o; o >>= 1) v += __shfl_xor_sync(0xffffffffu, v, o);
    __syncthreads();
    if ((threadIdx.x & 31) == 0) red[threadIdx.x >> 5] = v;
    __syncthreads();
    float s = red[0];
#pragma unroll
    for (int i = 1; i < 8; ++i) s += red[i];
    return s;
}
__device__ __forceinline__ float blk_max(float v, float* red) {
#pragma unroll
    for (int o = 16; o; o >>= 1) v = fmaxf(v, __shfl_xor_sync(0xffffffffu, v, o));
    __syncthreads();
    if ((threadIdx.x & 31) == 0) red[threadIdx.x >> 5] = v;
    __syncthreads();
    float s = red[0];
#pragma unroll
    for (int i = 1; i < 8; ++i) s = fmaxf(s, red[i]);
    return s;
}

__global__ void __launch_bounds__(256, 1) ntm_kernel(
    const int* __restrict__ x, const float* __restrict__ emb,
    const float* __restrict__ W_ih, const float* __restrict__ W_hh,
    const float* __restrict__ b_ih, const float* __restrict__ b_hh,
    const float* __restrict__ key_W, const float* __restrict__ key_b,
    const float* __restrict__ beta_W, const float* __restrict__ beta_b,
    const float* __restrict__ gate_W, const float* __restrict__ gate_b,
    const float* __restrict__ shift_W, const float* __restrict__ shift_b,
    const float* __restrict__ gamma_W, const float* __restrict__ gamma_b,
    const float* __restrict__ erase_W, const float* __restrict__ erase_b,
    const float* __restrict__ add_W, const float* __restrict__ add_b,
    const float* __restrict__ out_W, const float* __restrict__ out_b,
    const float* __restrict__ mem_init, float* __restrict__ out)
{
    extern __shared__ float sm[];
    const int tid = threadIdx.x;
    const int b = blockIdx.x;

    float* mem   = sm;                 // [N_][PITCH]
    float* xin   = mem + N_ * PITCH;   // 448: [0,128)=emb, [128,192)=rv, [192,448)=h
    float* wprev = xin + 448;          // 256
    float* wga   = wprev + N_;         // 256
    float* keys  = wga + N_;           // 64
    float* er    = keys + M_;          // 64
    float* ad    = er + M_;            // 64
    float* rv    = ad + M_;            // 64
    float* rvp   = rv + M_;            // 256
    float* red   = rvp + N_;           // 8
    float* sc    = red + 8;            // 8 scalars

    // ---- init state ----
    for (int i = tid; i < N_ * M_; i += 256)
        mem[(i >> 6) * PITCH + (i & 63)] = mem_init[(size_t)b * N_ * M_ + i];
    xin[192 + tid] = 0.0f;   // h = 0
    wprev[tid] = 0.0f;       // rw = 0
    if (tid < M_) rv[tid] = 0.0f;
    float c_reg = 0.0f;

    // ---- hoisted per-thread constants ----
    const float bias0 = b_ih[tid]       + b_hh[tid];
    const float bias1 = b_ih[256 + tid] + b_hh[256 + tid];
    const float bias2 = b_ih[512 + tid] + b_hh[512 + tid];
    const float bias3 = b_ih[768 + tid] + b_hh[768 + tid];
    const float4* wih0 = (const float4*)(W_ih + (size_t)tid * 192);
    const float4* wih1 = (const float4*)(W_ih + (size_t)(256 + tid) * 192);
    const float4* wih2 = (const float4*)(W_ih + (size_t)(512 + tid) * 192);
    const float4* wih3 = (const float4*)(W_ih + (size_t)(768 + tid) * 192);
    const float4* whh0 = (const float4*)(W_hh + (size_t)tid * 256);
    const float4* whh1 = (const float4*)(W_hh + (size_t)(256 + tid) * 256);
    const float4* whh2 = (const float4*)(W_hh + (size_t)(512 + tid) * 256);
    const float4* whh3 = (const float4*)(W_hh + (size_t)(768 + tid) * 256);
    const float4* ow0 = (const float4*)(out_W + (size_t)tid * 320);
    const float4* ow1 = (const float4*)(out_W + (size_t)(256 + tid) * 320);
    const float ob0 = out_b[tid], ob1 = out_b[256 + tid];

    // head projection assignment: 198 outputs, one per thread
    const float4* hw4 = nullptr;
    float hbias = 0.0f;
    int hkind = -1, hm = 0;
    if (tid < 64)       { hw4 = (const float4*)(key_W   + (size_t)tid * C_);          hbias = key_b[tid];          hkind = 0; hm = tid; }
    else if (tid < 128) { hw4 = (const float4*)(erase_W + (size_t)(tid - 64) * C_);   hbias = erase_b[tid - 64];   hkind = 1; hm = tid - 64; }
    else if (tid < 192) { hw4 = (const float4*)(add_W   + (size_t)(tid - 128) * C_);  hbias = add_b[tid - 128];    hkind = 2; hm = tid - 128; }
    else if (tid == 192){ hw4 = (const float4*)beta_W;                                hbias = beta_b[0];           hkind = 3; }
    else if (tid == 193){ hw4 = (const float4*)gate_W;                                hbias = gate_b[0];           hkind = 4; }
    else if (tid == 194){ hw4 = (const float4*)gamma_W;                               hbias = gamma_b[0];          hkind = 5; }
    else if (tid < 198) { hw4 = (const float4*)(shift_W + (size_t)(tid - 195) * C_);  hbias = shift_b[tid - 195];  hkind = 6; hm = tid - 195; }
    __syncthreads();

    for (int t = 0; t < S_; ++t) {
        // ---- build input vector ----
        const int tok = x[b * S_ + t];
        if (tid < D_)            xin[tid] = emb[(size_t)tok * D_ + tid];
        else if (tid < D_ + M_)  xin[tid] = rv[tid - D_];
        __syncthreads();

        // ---- LSTM gates: thread tid computes rows {tid, 256+tid, 512+tid, 768+tid}
        float4 A0 = make_float4(0, 0, 0, 0), A1 = A0, A2 = A0, A3 = A0;
        {
            const float4* xv4 = (const float4*)xin;
#pragma unroll 4
            for (int k = 0; k < 48; ++k) {
                const float4 xv = xv4[k];
                const float4 v0 = wih0[k], v1 = wih1[k], v2 = wih2[k], v3 = wih3[k];
                A0.x += v0.x * xv.x; A0.y += v0.y * xv.y; A0.z += v0.z * xv.z; A0.w += v0.w * xv.w;
                A1.x += v1.x * xv.x; A1.y += v1.y * xv.y; A1.z += v1.z * xv.z; A1.w += v1.w * xv.w;
                A2.x += v2.x * xv.x; A2.y += v2.y * xv.y; A2.z += v2.z * xv.z; A2.w += v2.w * xv.w;
                A3.x += v3.x * xv.x; A3.y += v3.y * xv.y; A3.z += v3.z * xv.z; A3.w += v3.w * xv.w;
            }
            const float4* hv4 = (const float4*)(xin + 192);
#pragma unroll 4
            for (int k = 0; k < 64; ++k) {
                const float4 xv = hv4[k];
                const float4 v0 = whh0[k], v1 = whh1[k], v2 = whh2[k], v3 = whh3[k];
                A0.x += v0.x * xv.x; A0.y += v0.y * xv.y; A0.z += v0.z * xv.z; A0.w += v0.w * xv.w;
                A1.x += v1.x * xv.x; A1.y += v1.y * xv.y; A1.z += v1.z * xv.z; A1.w += v1.w * xv.w;
                A2.x += v2.x * xv.x; A2.y += v2.y * xv.y; A2.z += v2.z * xv.z; A2.w += v2.w * xv.w;
                A3.x += v3.x * xv.x; A3.y += v3.y * xv.y; A3.z += v3.z * xv.z; A3.w += v3.w * xv.w;
            }
        }
        const float g0 = bias0 + (A0.x + A0.y) + (A0.z + A0.w);
        const float g1 = bias1 + (A1.x + A1.y) + (A1.z + A1.w);
        const float g2 = bias2 + (A2.x + A2.y) + (A2.z + A2.w);
        const float g3 = bias3 + (A3.x + A3.y) + (A3.z + A3.w);
        __syncthreads();   // everyone done reading old h before overwrite

        // torch LSTMCell order: i, f, g, o
        const float ig = sigm(g0), fg = sigm(g1), gg = tanhf(g2), og = sigm(g3);
        c_reg = fg * c_reg + ig * gg;
        const float hv = og * tanhf(c_reg);
        xin[192 + tid] = hv;
        __syncthreads();

        // ---- head projections (198 dots of length 256) ----
        if (hkind >= 0) {
            float4 Acc = make_float4(0, 0, 0, 0);
            const float4* h4 = (const float4*)(xin + 192);
#pragma unroll 8
            for (int k = 0; k < 64; ++k) {
                const float4 w = hw4[k];
                const float4 h_ = h4[k];
                Acc.x += w.x * h_.x; Acc.y += w.y * h_.y;
                Acc.z += w.z * h_.z; Acc.w += w.w * h_.w;
            }
            const float d = hbias + (Acc.x + Acc.y) + (Acc.z + Acc.w);
            switch (hkind) {
                case 0: keys[hm] = d; break;
                case 1: er[hm] = sigm(d); break;
                case 2: ad[hm] = tanhf(d); break;
                case 3: sc[0] = softplus_(d); break;          // beta
                case 4: sc[1] = sigm(d); break;               // gate
                case 5: sc[2] = 1.0f + softplus_(d); break;   // gamma
                case 6: sc[4 + hm] = d; break;                // shift raw
            }
        }
        __syncthreads();

        // shift softmax (thread 0) + key L2 norm (warp 1)
        if (tid == 0) {
            const float s0 = sc[4], s1 = sc[5], s2 = sc[6];
            const float mx = fmaxf(s0, fmaxf(s1, s2));
            const float e0 = expf(s0 - mx), e1 = expf(s1 - mx), e2 = expf(s2 - mx);
            const float inv = 1.0f / (e0 + e1 + e2);
            sc[4] = e0 * inv; sc[5] = e1 * inv; sc[6] = e2 * inv;
        } else if (tid >= 32 && tid < 64) {
            const int l = tid - 32;
            float v = keys[l] * keys[l] + keys[l + 32] * keys[l + 32];
#pragma unroll
            for (int o = 16; o; o >>= 1) v += __shfl_xor_sync(0xffffffffu, v, o);
            if (l == 0) sc[3] = fmaxf(sqrtf(v), 1e-12f);
        }
        __syncthreads();

        const float beta = sc[0], gatev = sc[1], gammav = sc[2], knorm = sc[3];
        const float sh0 = sc[4], sh1 = sc[5], sh2 = sc[6];

        // ---- content addressing: cosine sim per slot (thread = slot) ----
        float dot = 0.0f, sq = 0.0f;
        {
            const float* mrow = mem + tid * PITCH;
#pragma unroll 8
            for (int m = 0; m < 64; ++m) {
                const float v = mrow[m];
                dot += v * keys[m];
                sq += v * v;
            }
        }
        const float sim = dot / (fmaxf(sqrtf(sq), 1e-12f) * knorm);
        const float logit = beta * sim;
        const float mx = blk_max(logit, red);
        const float e = expf(logit - mx);
        const float ssum = blk_sum(e, red);
        const float wc = e / ssum;
        const float wg = gatev * wc + (1.0f - gatev) * wprev[tid];
        wga[tid] = wg;
        __syncthreads();

        // circular conv over {-1,0,+1} then sharpening
        const float wt = sh0 * wga[(tid + 1) & 255] + sh1 * wg + sh2 * wga[(tid + 255) & 255];
        const float ws = powf(wt, gammav);
        const float wsum = blk_sum(ws, red);      // entry sync also fences wga reads
        const float w = ws / wsum;
        wprev[tid] = w;
        wga[tid] = w;
        __syncthreads();

        // ---- read vector rv = w @ mem (before write) ----
        {
            const int m = tid & 63, g = tid >> 6;
            const float* base = mem + (g * 64) * PITCH + m;
            const float* wp = wga + g * 64;
            float s = 0.0f;
#pragma unroll 8
            for (int n = 0; n < 64; ++n) s += wp[n] * base[n * PITCH];
            rvp[tid] = s;
        }
        __syncthreads();   // all mem reads done; rvp ready
        if (tid < 64) rv[tid] = (rvp[tid] + rvp[64 + tid]) + (rvp[128 + tid] + rvp[192 + tid]);

        // ---- memory erase/add (thread = slot row) ----
        {
            const float wn = wga[tid];
            float* mrow = mem + tid * PITCH;
#pragma unroll 8
            for (int m = 0; m < 64; ++m)
                mrow[m] = mrow[m] * (1.0f - wn * er[m]) + wn * ad[m];
        }
        __syncthreads();   // rv visible for logits

        // ---- output logits: [h(256) | rv(64)] @ out_W^T + out_b ----
        {
            const float4* h4 = (const float4*)(xin + 192);
            const float4* r4 = (const float4*)rv;
            float4 A = make_float4(0, 0, 0, 0), Bv = make_float4(0, 0, 0, 0);
#pragma unroll 4
            for (int k = 0; k < 64; ++k) {
                const float4 h_ = h4[k];
                const float4 w0 = ow0[k], w1 = ow1[k];
                A.x  += w0.x * h_.x; A.y  += w0.y * h_.y; A.z  += w0.z * h_.z; A.w  += w0.w * h_.w;
                Bv.x += w1.x * h_.x; Bv.y += w1.y * h_.y; Bv.z += w1.z * h_.z; Bv.w += w1.w * h_.w;
            }
#pragma unroll
            for (int k = 0; k < 16; ++k) {
                const float4 r_ = r4[k];
                const float4 w0 = ow0[64 + k], w1 = ow1[64 + k];
                A.x  += w0.x * r_.x; A.y  += w0.y * r_.y; A.z  += w0.z * r_.z; A.w  += w0.w * r_.w;
                Bv.x += w1.x * r_.x; Bv.y += w1.y * r_.y; Bv.z += w1.z * r_.z; Bv.w += w1.w * r_.w;
            }
            float* orow = out + ((size_t)b * S_ + t) * V_;
            orow[tid]       = ob0 + (A.x + A.y) + (A.z + A.w);
            orow[256 + tid] = ob1 + (Bv.x + Bv.y) + (Bv.z + Bv.w);
        }
        __syncthreads();
    }
}

extern "C" void kernel_launch(void* const* d_in, const int* in_sizes, int n_in,
                              void* d_out, int out_size)
{
    const int*   x       = (const int*)d_in[0];
    const float* emb     = (const float*)d_in[1];
    const float* W_ih    = (const float*)d_in[2];
    const float* W_hh    = (const float*)d_in[3];
    const float* b_ih    = (const float*)d_in[4];
    const float* b_hh    = (const float*)d_in[5];
    const float* key_W   = (const float*)d_in[6];
    const float* key_b   = (const float*)d_in[7];
    const float* beta_W  = (const float*)d_in[8];
    const float* beta_b  = (const float*)d_in[9];
    const float* gate_W  = (const float*)d_in[10];
    const float* gate_b  = (const float*)d_in[11];
    const float* shift_W = (const float*)d_in[12];
    const float* shift_b = (const float*)d_in[13];
    const float* gamma_W = (const float*)d_in[14];
    const float* gamma_b = (const float*)d_in[15];
    const float* erase_W = (const float*)d_in[16];
    const float* erase_b = (const float*)d_in[17];
    const float* add_W   = (const float*)d_in[18];
    const float* add_b   = (const float*)d_in[19];
    const float* out_W   = (const float*)d_in[20];
    const float* out_b   = (const float*)d_in[21];
    const float* mem_init= (const float*)d_in[22];
    float* out = (float*)d_out;

    cudaFuncSetAttribute(ntm_kernel, cudaFuncAttributeMaxDynamicSharedMemorySize,
                         (int)SMEM_BYTES);
    ntm_kernel<<<B_, 256, SMEM_BYTES>>>(
        x, emb, W_ih, W_hh, b_ih, b_hh,
        key_W, key_b, beta_W, beta_b, gate_W, gate_b,
        shift_W, shift_b, gamma_W, gamma_b,
        erase_W, erase_b, add_W, add_b,
        out_W, out_b, mem_init, out);
}

// round 7
// speedup vs baseline: 1.5472x; 1.5472x over previous
#include <cuda_runtime.h>
#include <math.h>
#include <float.h>

namespace {
constexpr int B_ = 64;    // batch
constexpr int S_ = 128;   // seq len
constexpr int D_ = 128;   // embed dim
constexpr int V_ = 512;   // vocab
constexpr int C_ = 256;   // controller size
constexpr int N_ = 256;   // memory slots
constexpr int M_ = 64;    // memory width
constexpr int PITCH = 65; // smem pitch for mem (bank-conflict-free rows)
constexpr int T_ = 1024;  // threads per CTA

constexpr int SMEM_FLOATS =
    N_ * PITCH   // mem                     16640
    + 512        // xin = [emb128 | rv64 | h256 | rv64]
    + 1024       // garr: gate preacts, reused as rvp[16][64]
    + N_         // wprev
    + N_         // wga
    + M_ * 3     // keys, er, ad
    + 32         // red
    + 8;         // sc scalars
constexpr size_t SMEM_BYTES = SMEM_FLOATS * sizeof(float);
}

__device__ __forceinline__ float sigm(float x) { return 1.0f / (1.0f + expf(-x)); }
__device__ __forceinline__ float softplus_(float x) { return log1pf(expf(x)); }
__device__ __forceinline__ float hsum4(float4 a) { return (a.x + a.y) + (a.z + a.w); }

// Block reductions over 1024 threads (32 warps). Entry sync protects `red`.
__device__ __forceinline__ float blk_sum(float v, float* red) {
#pragma unroll
    for (int o = 16; o; o >>= 1) v += __shfl_xor_sync(0xffffffffu, v, o);
    __syncthreads();
    if ((threadIdx.x & 31) == 0) red[threadIdx.x >> 5] = v;
    __syncthreads();
    float s = red[0];
#pragma unroll
    for (int i = 1; i < 32; ++i) s += red[i];
    return s;
}
__device__ __forceinline__ float blk_max(float v, float* red) {
#pragma unroll
    for (int o = 16; o; o >>= 1) v = fmaxf(v, __shfl_xor_sync(0xffffffffu, v, o));
    __syncthreads();
    if ((threadIdx.x & 31) == 0) red[threadIdx.x >> 5] = v;
    __syncthreads();
    float s = red[0];
#pragma unroll
    for (int i = 1; i < 32; ++i) s = fmaxf(s, red[i]);
    return s;
}

__global__ void __launch_bounds__(T_, 1) ntm_kernel(
    const int* __restrict__ x, const float* __restrict__ emb,
    const float* __restrict__ W_ih, const float* __restrict__ W_hh,
    const float* __restrict__ b_ih, const float* __restrict__ b_hh,
    const float* __restrict__ key_W, const float* __restrict__ key_b,
    const float* __restrict__ beta_W, const float* __restrict__ beta_b,
    const float* __restrict__ gate_W, const float* __restrict__ gate_b,
    const float* __restrict__ shift_W, const float* __restrict__ shift_b,
    const float* __restrict__ gamma_W, const float* __restrict__ gamma_b,
    const float* __restrict__ erase_W, const float* __restrict__ erase_b,
    const float* __restrict__ add_W, const float* __restrict__ add_b,
    const float* __restrict__ out_W, const float* __restrict__ out_b,
    const float* __restrict__ mem_init, float* __restrict__ out)
{
    extern __shared__ float sm[];
    const int tid = threadIdx.x;
    const int b = blockIdx.x;

    float* mem   = sm;                 // [N_][PITCH]
    float* xin   = mem + N_ * PITCH;   // 512: [emb128 | rv64 | h256 | rv64]
    float* garr  = xin + 512;          // 1024 gate preacts / rvp
    float* wprev = garr + 1024;        // 256
    float* wga   = wprev + N_;         // 256
    float* keys  = wga + N_;           // 64
    float* er    = keys + M_;          // 64
    float* ad    = er + M_;            // 64
    float* red   = ad + M_;            // 32
    float* sc    = red + 32;           // 8 scalars: beta,gate,gamma,knorm,sh0..2

    // ---- init state ----
    for (int i = tid; i < N_ * M_; i += T_)
        mem[(i >> 6) * PITCH + (i & 63)] = mem_init[(size_t)b * N_ * M_ + i];
    if (tid < 256) { xin[192 + tid] = 0.0f; wprev[tid] = 0.0f; }
    if (tid < 64)  xin[448 + tid] = 0.0f;   // rv = 0
    float c_reg = 0.0f;                      // valid for tid < 256

    // ---- hoisted constants ----
    // LSTM: one gate-row per thread
    const float  gbias = b_ih[tid] + b_hh[tid];
    const float4* wih4 = (const float4*)(W_ih + (size_t)tid * 192);
    const float4* whh4 = (const float4*)(W_hh + (size_t)tid * 256);

    // Output proj: row = tid>>1, half = tid&1 (40 float4 each)
    const int orow = tid >> 1, ohalf = tid & 1;
    const float4* ow4 = (const float4*)(out_W + (size_t)orow * 320) + ohalf * 40;
    const float  ob   = out_b[orow];

    // Heads: 198 outputs, 2 threads each (warps 0..12 = threads < 416)
    const float4* hw4 = (const float4*)key_W;
    float hbias = 0.0f;
    int hkind = -1, hm = 0;
    if (tid < 416) {
        const int ho = tid >> 1;
        if (ho < 64)       { hw4 = (const float4*)(key_W   + (size_t)ho * C_);          hbias = key_b[ho];          hkind = 0; hm = ho; }
        else if (ho < 128) { hw4 = (const float4*)(erase_W + (size_t)(ho - 64) * C_);   hbias = erase_b[ho - 64];   hkind = 1; hm = ho - 64; }
        else if (ho < 192) { hw4 = (const float4*)(add_W   + (size_t)(ho - 128) * C_);  hbias = add_b[ho - 128];    hkind = 2; hm = ho - 128; }
        else if (ho == 192){ hw4 = (const float4*)beta_W;                               hbias = beta_b[0];          hkind = 3; }
        else if (ho == 193){ hw4 = (const float4*)gate_W;                               hbias = gate_b[0];          hkind = 4; }
        else if (ho == 194){ hw4 = (const float4*)gamma_W;                              hbias = gamma_b[0];         hkind = 5; }
        else if (ho < 198) { hw4 = (const float4*)(shift_W + (size_t)(ho - 195) * C_);  hbias = shift_b[ho - 195];  hkind = 6; hm = ho - 195; }
        hw4 += (tid & 1) * 32;
    }
    __syncthreads();

    for (int t = 0; t < S_; ++t) {
        // ---- phase 0: build input vector [emb | rv] ----
        const int tok = x[b * S_ + t];
        if (tid < D_)            xin[tid] = emb[(size_t)tok * D_ + tid];
        else if (tid < D_ + M_)  xin[tid] = xin[320 + tid];  // rv from xin[448..]
        __syncthreads();

        // ---- phase 1: LSTM gate preacts, 1 row per thread ----
        {
            float4 a0 = make_float4(0, 0, 0, 0), a1 = a0;
            const float4* xv4 = (const float4*)xin;
#pragma unroll
            for (int k = 0; k < 48; k += 2) {
                const float4 w0 = wih4[k], w1 = wih4[k + 1];
                const float4 v0 = xv4[k],  v1 = xv4[k + 1];
                a0.x += w0.x * v0.x; a0.y += w0.y * v0.y; a0.z += w0.z * v0.z; a0.w += w0.w * v0.w;
                a1.x += w1.x * v1.x; a1.y += w1.y * v1.y; a1.z += w1.z * v1.z; a1.w += w1.w * v1.w;
            }
            const float4* hv4 = (const float4*)(xin + 192);
#pragma unroll
            for (int k = 0; k < 64; k += 2) {
                const float4 w0 = whh4[k], w1 = whh4[k + 1];
                const float4 v0 = hv4[k],  v1 = hv4[k + 1];
                a0.x += w0.x * v0.x; a0.y += w0.y * v0.y; a0.z += w0.z * v0.z; a0.w += w0.w * v0.w;
                a1.x += w1.x * v1.x; a1.y += w1.y * v1.y; a1.z += w1.z * v1.z; a1.w += w1.w * v1.w;
            }
            garr[tid] = gbias + hsum4(a0) + hsum4(a1);
        }
        __syncthreads();

        // ---- cell update (threads < 256; torch gate order i,f,g,o) ----
        if (tid < 256) {
            const float ig = sigm(garr[tid]);
            const float fg = sigm(garr[256 + tid]);
            const float gg = tanhf(garr[512 + tid]);
            const float og = sigm(garr[768 + tid]);
            c_reg = fg * c_reg + ig * gg;
            xin[192 + tid] = og * tanhf(c_reg);
        }
        __syncthreads();

        // ---- phase 2: head projections (2 threads per output) ----
        if (tid < 416) {
            float4 acc = make_float4(0, 0, 0, 0);
            const float4* h4 = (const float4*)(xin + 192) + (tid & 1) * 32;
#pragma unroll
            for (int k = 0; k < 32; ++k) {
                const float4 w = hw4[k];
                const float4 h_ = h4[k];
                acc.x += w.x * h_.x; acc.y += w.y * h_.y;
                acc.z += w.z * h_.z; acc.w += w.w * h_.w;
            }
            float d = hsum4(acc);
            d += __shfl_down_sync(0xffffffffu, d, 1);
            if (hkind >= 0 && (tid & 1) == 0) {
                d += hbias;
                switch (hkind) {
                    case 0: keys[hm] = d; break;
                    case 1: er[hm] = sigm(d); break;
                    case 2: ad[hm] = tanhf(d); break;
                    case 3: sc[0] = softplus_(d); break;
                    case 4: sc[1] = sigm(d); break;
                    case 5: sc[2] = 1.0f + softplus_(d); break;
                    case 6: sc[4 + hm] = d; break;
                }
            }
        }
        __syncthreads();

        // ---- phase 3: shift softmax (t0) + key norm (warp 1) ----
        if (tid == 0) {
            const float s0 = sc[4], s1 = sc[5], s2 = sc[6];
            const float mx = fmaxf(s0, fmaxf(s1, s2));
            const float e0 = expf(s0 - mx), e1 = expf(s1 - mx), e2 = expf(s2 - mx);
            const float inv = 1.0f / (e0 + e1 + e2);
            sc[4] = e0 * inv; sc[5] = e1 * inv; sc[6] = e2 * inv;
        } else if (tid >= 32 && tid < 64) {
            const int l = tid - 32;
            float v = keys[l] * keys[l] + keys[l + 32] * keys[l + 32];
#pragma unroll
            for (int o = 16; o; o >>= 1) v += __shfl_xor_sync(0xffffffffu, v, o);
            if (l == 0) sc[3] = fmaxf(sqrtf(v), 1e-12f);
        }
        __syncthreads();

        const float beta = sc[0], gatev = sc[1], gammav = sc[2], knorm = sc[3];
        const float sh0 = sc[4], sh1 = sc[5], sh2 = sc[6];

        // ---- phase 4: content addressing (4 threads per slot) ----
        {
            const int slot = tid >> 2, q = tid & 3;
            const float* mrow = mem + slot * PITCH + q * 16;
            const float* kq = keys + q * 16;
            float dot = 0.0f, sq = 0.0f;
#pragma unroll
            for (int j = 0; j < 16; ++j) {
                const float v = mrow[j];
                dot += v * kq[j];
                sq += v * v;
            }
            dot += __shfl_xor_sync(0xffffffffu, dot, 1);
            dot += __shfl_xor_sync(0xffffffffu, dot, 2);
            sq  += __shfl_xor_sync(0xffffffffu, sq, 1);
            sq  += __shfl_xor_sync(0xffffffffu, sq, 2);
            const float sim = dot / (fmaxf(sqrtf(sq), 1e-12f) * knorm);
            const float logit = beta * sim;
            const float mx = blk_max(q == 0 ? logit : -FLT_MAX, red);
            const float e = expf(logit - mx);
            const float ssum = blk_sum(q == 0 ? e : 0.0f, red);
            if (q == 0) {
                const float wc = e / ssum;
                wga[slot] = gatev * wc + (1.0f - gatev) * wprev[slot];
            }
        }
        __syncthreads();

        // ---- phase 5: circular conv + sharpening (threads < 256) ----
        {
            float ws = 0.0f;
            if (tid < 256) {
                const float wt = sh0 * wga[(tid + 1) & 255] + sh1 * wga[tid]
                               + sh2 * wga[(tid + 255) & 255];
                ws = powf(wt, gammav);
            }
            const float wsum = blk_sum(ws, red);   // internal syncs fence wga reads
            if (tid < 256) {
                const float w = ws / wsum;
                wprev[tid] = w;
                wga[tid] = w;
            }
        }
        __syncthreads();

        // ---- phase 6: rv = w @ mem (16 n-groups x 64 m) ----
        {
            const int m = tid & 63, g = tid >> 6;
            const float* base = mem + (g * 16) * PITCH + m;
            const float* wp = wga + g * 16;
            float s = 0.0f;
#pragma unroll
            for (int n = 0; n < 16; ++n) s += wp[n] * base[n * PITCH];
            garr[g * 64 + m] = s;
        }
        __syncthreads();   // mem reads done; partials ready

        if (tid < 64) {
            float r = 0.0f;
#pragma unroll
            for (int g = 0; g < 16; ++g) r += garr[g * 64 + tid];
            xin[448 + tid] = r;
        }

        // ---- phase 7: memory erase/add (4 threads per slot) ----
        {
            const int slot = tid >> 2, q = tid & 3;
            const float wn = wga[slot];
            float* mrow = mem + slot * PITCH + q * 16;
            const float* eq = er + q * 16;
            const float* aq = ad + q * 16;
#pragma unroll
            for (int j = 0; j < 16; ++j)
                mrow[j] = mrow[j] * (1.0f - wn * eq[j]) + wn * aq[j];
        }
        __syncthreads();   // rv + mem visible

        // ---- phase 8: output logits (2 threads per row over [h|rv]) ----
        {
            float4 acc = make_float4(0, 0, 0, 0);
            const float4* v4 = (const float4*)(xin + 192) + ohalf * 40;
#pragma unroll
            for (int k = 0; k < 40; ++k) {
                const float4 w = ow4[k];
                const float4 v = v4[k];
                acc.x += w.x * v.x; acc.y += w.y * v.y;
                acc.z += w.z * v.z; acc.w += w.w * v.w;
            }
            float d = hsum4(acc);
            d += __shfl_down_sync(0xffffffffu, d, 1);
            if (ohalf == 0)
                out[((size_t)b * S_ + t) * V_ + orow] = d + ob;
        }
        // no sync needed: next phase 0 writes xin[0..191], disjoint from
        // phase 8's reads (xin[192..511]); xin[448..] next written in phase 6.
    }
}

extern "C" void kernel_launch(void* const* d_in, const int* in_sizes, int n_in,
                              void* d_out, int out_size)
{
    const int*   x       = (const int*)d_in[0];
    const float* emb     = (const float*)d_in[1];
    const float* W_ih    = (const float*)d_in[2];
    const float* W_hh    = (const float*)d_in[3];
    const float* b_ih    = (const float*)d_in[4];
    const float* b_hh    = (const float*)d_in[5];
    const float* key_W   = (const float*)d_in[6];
    const float* key_b   = (const float*)d_in[7];
    const float* beta_W  = (const float*)d_in[8];
    const float* beta_b  = (const float*)d_in[9];
    const float* gate_W  = (const float*)d_in[10];
    const float* gate_b  = (const float*)d_in[11];
    const float* shift_W = (const float*)d_in[12];
    const float* shift_b = (const float*)d_in[13];
    const float* gamma_W = (const float*)d_in[14];
    const float* gamma_b = (const float*)d_in[15];
    const float* erase_W = (const float*)d_in[16];
    const float* erase_b = (const float*)d_in[17];
    const float* add_W   = (const float*)d_in[18];
    const float* add_b   = (const float*)d_in[19];
    const float* out_W   = (const float*)d_in[20];
    const float* out_b   = (const float*)d_in[21];
    const float* mem_init= (const float*)d_in[22];
    float* out = (float*)d_out;

    cudaFuncSetAttribute(ntm_kernel, cudaFuncAttributeMaxDynamicSharedMemorySize,
                         (int)SMEM_BYTES);
    ntm_kernel<<<B_, T_, SMEM_BYTES>>>(
        x, emb, W_ih, W_hh, b_ih, b_hh,
        key_W, key_b, beta_W, beta_b, gate_W, gate_b,
        shift_W, shift_b, gamma_W, gamma_b,
        erase_W, erase_b, add_W, add_b,
        out_W, out_b, mem_init, out);
}